// round 2
// baseline (speedup 1.0000x reference)
#include <cuda_runtime.h>
#include <math.h>

// Problem constants
#define CIN   64
#define COUT  128
#define HH    128
#define WW    128
#define NB    32
#define TPB   256
#define IC_CHUNK 8
#define NCHUNK (CIN / IC_CHUNK)

// smem: x tile [64 ic][3 rows][128 cols] + weight chunk [8*9][128 oc]
#define XS_FLOATS (CIN * 3 * WW)            // 24576
#define WS_FLOATS (IC_CHUNK * 9 * COUT)     // 9216
#define SMEM_BYTES ((XS_FLOATS + WS_FLOATS) * 4)   // 135168

__device__ __forceinline__ float gelu_tanh(float y) {
    float u = 0.7978845608f * (y + 0.044715f * y * y * y);
    return 0.5f * y * (1.0f + tanhf(u));
}

__device__ __forceinline__ unsigned long long pack2(float a) {
    unsigned long long r;
    asm("mov.b64 %0, {%1, %1};" : "=l"(r) : "f"(a));
    return r;
}

__device__ __forceinline__ void fma2(unsigned long long& d,
                                     unsigned long long a,
                                     unsigned long long b) {
    asm("fma.rn.f32x2 %0, %1, %2, %0;" : "+l"(d) : "l"(a), "l"(b));
}

extern __shared__ float smem[];

__global__ __launch_bounds__(TPB, 1)
void fused_convt_gelu_gn_kernel(const float* __restrict__ x,
                                const float* __restrict__ w,
                                const float* __restrict__ bias,
                                const float* __restrict__ gnw,
                                const float* __restrict__ gnb,
                                float* __restrict__ out) {
    float* xs = smem;                 // [ic*3 + r][col]
    float* ws = smem + XS_FLOATS;     // [(icl*3+kh)*3+kw][oc]

    const int h = blockIdx.x;
    const int n = blockIdx.y;
    const int t = threadIdx.x;
    const int ocg = t >> 4;           // 0..15  -> oc base = ocg*8
    const int cg  = t & 15;           // 0..15  -> col base = cg*8
    const int o0 = ocg * 8;
    const int c0 = cg * 8;

    // ---- load x tile: global rows h-2+r, zero-padded at top boundary ----
    {
        const float* xb = x + (size_t)n * CIN * HH * WW;
        // 192 rows * 32 float4 = 6144 float4
        for (int i = t; i < (CIN * 3 * WW) / 4; i += TPB) {
            int col4 = i & 31;
            int row  = i >> 5;                 // ic*3 + r
            int ic = row / 3, r = row - ic * 3;
            int gh = h - 2 + r;
            float4 v = make_float4(0.f, 0.f, 0.f, 0.f);
            if (gh >= 0)
                v = *(const float4*)(xb + ((size_t)ic * HH + gh) * WW + col4 * 4);
            *(float4*)(xs + row * WW + col4 * 4) = v;
        }
    }

    // ---- accumulators: 8 cols x 4 oc-pairs of f32x2 ----
    unsigned long long acc[8][4];
#pragma unroll
    for (int j = 0; j < 8; j++)
#pragma unroll
        for (int p = 0; p < 4; p++) acc[j][p] = 0ULL;

#pragma unroll 1
    for (int ch = 0; ch < NCHUNK; ch++) {
        __syncthreads();   // prev-chunk readers done before ws overwrite
        {
            const int ic0 = ch * IC_CHUNK;
#pragma unroll
            for (int i = 0; i < 4; i++) {
                int f = t + i * TPB;           // 0..1023 = icl*128 + oc
                int icl = f >> 7, oc = f & 127;
                const float* wg = w + ((size_t)(ic0 + icl) * COUT + oc) * 9;
#pragma unroll
                for (int q = 0; q < 9; q++)
                    ws[(icl * 9 + q) * COUT + oc] = wg[q];
            }
        }
        __syncthreads();

#pragma unroll 1
        for (int icl = 0; icl < IC_CHUNK; icl++) {
            const float* xrowbase = xs + (size_t)((ch * IC_CHUNK + icl) * 3) * WW;
#pragma unroll
            for (int r = 0; r < 3; r++) {
                const float* xr = xrowbase + r * WW + c0;
                float xv[10];                      // xv[i] = x[c0-2+i]
                if (cg) {
                    float4 a = *(const float4*)(xr - 4);
                    xv[0] = a.z; xv[1] = a.w;
                } else {
                    xv[0] = 0.f; xv[1] = 0.f;
                }
                float4 bq = *(const float4*)(xr);
                xv[2] = bq.x; xv[3] = bq.y; xv[4] = bq.z; xv[5] = bq.w;
                float4 cq = *(const float4*)(xr + 4);
                xv[6] = cq.x; xv[7] = cq.y; xv[8] = cq.z; xv[9] = cq.w;

                unsigned long long xp[10];
#pragma unroll
                for (int i = 0; i < 10; i++) xp[i] = pack2(xv[i]);

                const int kh = 2 - r;
#pragma unroll
                for (int kw = 0; kw < 3; kw++) {
                    const unsigned long long* wr = (const unsigned long long*)
                        (ws + ((icl * 3 + kh) * 3 + kw) * COUT + o0);
                    unsigned long long wp[4];
#pragma unroll
                    for (int p = 0; p < 4; p++) wp[p] = wr[p];
#pragma unroll
                    for (int j = 0; j < 8; j++) {
                        unsigned long long xx = xp[j + 2 - kw];
#pragma unroll
                        for (int p = 0; p < 4; p++) fma2(acc[j][p], xx, wp[p]);
                    }
                }
            }
        }
    }

    // ---- epilogue: bias + tanh-GELU ----
    float bb[8], gwv[8], gbv[8];
#pragma unroll
    for (int p = 0; p < 8; p++) {
        bb[p]  = __ldg(bias + o0 + p);
        gwv[p] = __ldg(gnw  + o0 + p);
        gbv[p] = __ldg(gnb  + o0 + p);
    }

    float g[8][8];  // [col j][oc local]
#pragma unroll
    for (int j = 0; j < 8; j++) {
#pragma unroll
        for (int p = 0; p < 4; p++) {
            float lo, hi;
            asm("mov.b64 {%0, %1}, %2;" : "=f"(lo), "=f"(hi) : "l"(acc[j][p]));
            g[j][2 * p]     = gelu_tanh(lo + bb[2 * p]);
            g[j][2 * p + 1] = gelu_tanh(hi + bb[2 * p + 1]);
        }
    }

    // ---- per-pixel group stats (group = 16 oc = this thread + partner t^16) ----
    float mean[8], rstd[8];
#pragma unroll
    for (int j = 0; j < 8; j++) {
        float s1 = 0.f, s2 = 0.f;
#pragma unroll
        for (int p = 0; p < 8; p++) { s1 += g[j][p]; s2 += g[j][p] * g[j][p]; }
        s1 += __shfl_xor_sync(0xffffffffu, s1, 16);
        s2 += __shfl_xor_sync(0xffffffffu, s2, 16);
        float m = s1 * (1.0f / 16.0f);
        float v = s2 * (1.0f / 16.0f) - m * m;
        mean[j] = m;
        rstd[j] = rsqrtf(v + 1e-5f);
    }

    // ---- normalize + affine + coalesced float4 stores ----
#pragma unroll
    for (int p = 0; p < 8; p++) {
        float o[8];
#pragma unroll
        for (int j = 0; j < 8; j++)
            o[j] = (g[j][p] - mean[j]) * rstd[j] * gwv[p] + gbv[p];
        float* dst = out + (((size_t)n * COUT + (o0 + p)) * HH + h) * WW + c0;
        *(float4*)(dst)     = make_float4(o[0], o[1], o[2], o[3]);
        *(float4*)(dst + 4) = make_float4(o[4], o[5], o[6], o[7]);
    }
}

extern "C" void kernel_launch(void* const* d_in, const int* in_sizes, int n_in,
                              void* d_out, int out_size) {
    const float* x   = (const float*)d_in[0];
    const float* w   = (const float*)d_in[1];
    const float* b   = (const float*)d_in[2];
    const float* gnw = (const float*)d_in[3];
    const float* gnb = (const float*)d_in[4];
    float* out = (float*)d_out;

    cudaFuncSetAttribute(fused_convt_gelu_gn_kernel,
                         cudaFuncAttributeMaxDynamicSharedMemorySize, SMEM_BYTES);
    dim3 grid(HH, NB);
    fused_convt_gelu_gn_kernel<<<grid, TPB, SMEM_BYTES>>>(x, w, b, gnw, gnb, out);
}

// round 3
// speedup vs baseline: 1.0006x; 1.0006x over previous
#include <cuda_runtime.h>
#include <math.h>

// Problem constants
#define CIN   64
#define COUT  128
#define HH    128
#define WW    128
#define NB    32
#define TPB   256
#define IC_CHUNK 8
#define NCHUNK (CIN / IC_CHUNK)

// smem: x tile [64 ic][3 rows][128 cols] + weight chunk [8*9][128 oc]
#define XS_FLOATS (CIN * 3 * WW)            // 24576
#define WS_FLOATS (IC_CHUNK * 9 * COUT)     // 9216
#define SMEM_BYTES ((XS_FLOATS + WS_FLOATS) * 4)   // 135168

__device__ __forceinline__ float gelu_tanh(float y) {
    float u = 0.7978845608f * (y + 0.044715f * y * y * y);
    return 0.5f * y * (1.0f + tanhf(u));
}

__device__ __forceinline__ unsigned long long pack2(float a) {
    unsigned long long r;
    asm("mov.b64 %0, {%1, %1};" : "=l"(r) : "f"(a));
    return r;
}

__device__ __forceinline__ void fma2(unsigned long long& d,
                                     unsigned long long a,
                                     unsigned long long b) {
    asm("fma.rn.f32x2 %0, %1, %2, %0;" : "+l"(d) : "l"(a), "l"(b));
}

extern __shared__ float smem[];

__global__ __launch_bounds__(TPB, 1)
void fused_convt_gelu_gn_kernel(const float* __restrict__ x,
                                const float* __restrict__ w,
                                const float* __restrict__ bias,
                                const float* __restrict__ gnw,
                                const float* __restrict__ gnb,
                                float* __restrict__ out) {
    float* xs = smem;                 // [ic*3 + r][col]
    float* ws = smem + XS_FLOATS;     // [(icl*3+kh)*3+kw][oc]

    const int h = blockIdx.x;
    const int n = blockIdx.y;
    const int t = threadIdx.x;
    const int ocg = t >> 4;           // 0..15  -> oc base = ocg*8
    const int cg  = t & 15;           // 0..15  -> col base = cg*8
    const int o0 = ocg * 8;
    const int c0 = cg * 8;

    // ---- load x tile: global rows h-2+r, zero-padded at top boundary ----
    {
        const float* xb = x + (size_t)n * CIN * HH * WW;
        // 192 rows * 32 float4 = 6144 float4
        for (int i = t; i < (CIN * 3 * WW) / 4; i += TPB) {
            int col4 = i & 31;
            int row  = i >> 5;                 // ic*3 + r
            int ic = row / 3, r = row - ic * 3;
            int gh = h - 2 + r;
            float4 v = make_float4(0.f, 0.f, 0.f, 0.f);
            if (gh >= 0)
                v = *(const float4*)(xb + ((size_t)ic * HH + gh) * WW + col4 * 4);
            *(float4*)(xs + row * WW + col4 * 4) = v;
        }
    }

    // ---- accumulators: 8 cols x 4 oc-pairs of f32x2 ----
    unsigned long long acc[8][4];
#pragma unroll
    for (int j = 0; j < 8; j++)
#pragma unroll
        for (int p = 0; p < 4; p++) acc[j][p] = 0ULL;

#pragma unroll 1
    for (int ch = 0; ch < NCHUNK; ch++) {
        __syncthreads();   // prev-chunk readers done before ws overwrite
        {
            const int ic0 = ch * IC_CHUNK;
#pragma unroll
            for (int i = 0; i < 4; i++) {
                int f = t + i * TPB;           // 0..1023 = icl*128 + oc
                int icl = f >> 7, oc = f & 127;
                const float* wg = w + ((size_t)(ic0 + icl) * COUT + oc) * 9;
#pragma unroll
                for (int q = 0; q < 9; q++)
                    ws[(icl * 9 + q) * COUT + oc] = wg[q];
            }
        }
        __syncthreads();

#pragma unroll 1
        for (int icl = 0; icl < IC_CHUNK; icl++) {
            const float* xrowbase = xs + (size_t)((ch * IC_CHUNK + icl) * 3) * WW;
#pragma unroll
            for (int r = 0; r < 3; r++) {
                const float* xr = xrowbase + r * WW + c0;
                float xv[10];                      // xv[i] = x[c0-2+i]
                if (cg) {
                    float4 a = *(const float4*)(xr - 4);
                    xv[0] = a.z; xv[1] = a.w;
                } else {
                    xv[0] = 0.f; xv[1] = 0.f;
                }
                float4 bq = *(const float4*)(xr);
                xv[2] = bq.x; xv[3] = bq.y; xv[4] = bq.z; xv[5] = bq.w;
                float4 cq = *(const float4*)(xr + 4);
                xv[6] = cq.x; xv[7] = cq.y; xv[8] = cq.z; xv[9] = cq.w;

                unsigned long long xp[10];
#pragma unroll
                for (int i = 0; i < 10; i++) xp[i] = pack2(xv[i]);

                const int kh = 2 - r;
#pragma unroll
                for (int kw = 0; kw < 3; kw++) {
                    const unsigned long long* wr = (const unsigned long long*)
                        (ws + ((icl * 3 + kh) * 3 + kw) * COUT + o0);
                    unsigned long long wp[4];
#pragma unroll
                    for (int p = 0; p < 4; p++) wp[p] = wr[p];
#pragma unroll
                    for (int j = 0; j < 8; j++) {
                        unsigned long long xx = xp[j + 2 - kw];
#pragma unroll
                        for (int p = 0; p < 4; p++) fma2(acc[j][p], xx, wp[p]);
                    }
                }
            }
        }
    }

    // ---- epilogue: bias + tanh-GELU ----
    float bb[8], gwv[8], gbv[8];
#pragma unroll
    for (int p = 0; p < 8; p++) {
        bb[p]  = __ldg(bias + o0 + p);
        gwv[p] = __ldg(gnw  + o0 + p);
        gbv[p] = __ldg(gnb  + o0 + p);
    }

    float g[8][8];  // [col j][oc local]
#pragma unroll
    for (int j = 0; j < 8; j++) {
#pragma unroll
        for (int p = 0; p < 4; p++) {
            float lo, hi;
            asm("mov.b64 {%0, %1}, %2;" : "=f"(lo), "=f"(hi) : "l"(acc[j][p]));
            g[j][2 * p]     = gelu_tanh(lo + bb[2 * p]);
            g[j][2 * p + 1] = gelu_tanh(hi + bb[2 * p + 1]);
        }
    }

    // ---- per-pixel group stats (group = 16 oc = this thread + partner t^16) ----
    float mean[8], rstd[8];
#pragma unroll
    for (int j = 0; j < 8; j++) {
        float s1 = 0.f, s2 = 0.f;
#pragma unroll
        for (int p = 0; p < 8; p++) { s1 += g[j][p]; s2 += g[j][p] * g[j][p]; }
        s1 += __shfl_xor_sync(0xffffffffu, s1, 16);
        s2 += __shfl_xor_sync(0xffffffffu, s2, 16);
        float m = s1 * (1.0f / 16.0f);
        float v = s2 * (1.0f / 16.0f) - m * m;
        mean[j] = m;
        rstd[j] = rsqrtf(v + 1e-5f);
    }

    // ---- normalize + affine + coalesced float4 stores ----
#pragma unroll
    for (int p = 0; p < 8; p++) {
        float o[8];
#pragma unroll
        for (int j = 0; j < 8; j++)
            o[j] = (g[j][p] - mean[j]) * rstd[j] * gwv[p] + gbv[p];
        float* dst = out + (((size_t)n * COUT + (o0 + p)) * HH + h) * WW + c0;
        *(float4*)(dst)     = make_float4(o[0], o[1], o[2], o[3]);
        *(float4*)(dst + 4) = make_float4(o[4], o[5], o[6], o[7]);
    }
}

extern "C" void kernel_launch(void* const* d_in, const int* in_sizes, int n_in,
                              void* d_out, int out_size) {
    const float* x   = (const float*)d_in[0];
    const float* w   = (const float*)d_in[1];
    const float* b   = (const float*)d_in[2];
    const float* gnw = (const float*)d_in[3];
    const float* gnb = (const float*)d_in[4];
    float* out = (float*)d_out;

    cudaFuncSetAttribute(fused_convt_gelu_gn_kernel,
                         cudaFuncAttributeMaxDynamicSharedMemorySize, SMEM_BYTES);
    dim3 grid(HH, NB);
    fused_convt_gelu_gn_kernel<<<grid, TPB, SMEM_BYTES>>>(x, w, b, gnw, gnb, out);
}